// round 1
// baseline (speedup 1.0000x reference)
#include <cuda_runtime.h>

#define D_MODEL 2048
#define S_LEN   2048
#define N_HEADS 16
#define HD      128

// Scratch (allocation-free rule: __device__ globals)
__device__ __align__(16) float g_Q[S_LEN * D_MODEL];
__device__ __align__(16) float g_K[S_LEN * D_MODEL];
__device__ __align__(16) float g_V[S_LEN * D_MODEL];
__device__ __align__(16) float g_O[S_LEN * D_MODEL];

// ---------------------------------------------------------------------------
// C[M,N] = A[M,K] @ B[N,K]^T   (both row-major, K contiguous)
// 128x128 CTA tile, BK=16, 256 threads, 8x8 per-thread register tile.
// smem stored transposed As[k][m] with row stride 132 (16B-aligned, low-conflict).
// ---------------------------------------------------------------------------
__global__ __launch_bounds__(256, 2)
void gemm_nt_128(const float* __restrict__ A, const float* __restrict__ B,
                 float* __restrict__ C, int M, int N, int K)
{
    __shared__ __align__(16) float As[16 * 132];
    __shared__ __align__(16) float Bs[16 * 132];

    const int t  = threadIdx.x;
    const int tx = t & 15;
    const int ty = t >> 4;

    const float* Ab = A + (size_t)(blockIdx.y * 128) * K;
    const float* Bb = B + (size_t)(blockIdx.x * 128) * K;

    float acc[8][8];
#pragma unroll
    for (int i = 0; i < 8; i++)
#pragma unroll
        for (int j = 0; j < 8; j++) acc[i][j] = 0.f;

    const int lr = t >> 2;        // 0..63
    const int lk = (t & 3) << 2;  // 0,4,8,12

    for (int k0 = 0; k0 < K; k0 += 16) {
        float4 a0 = *(const float4*)(Ab + (size_t)lr        * K + (k0 + lk));
        float4 a1 = *(const float4*)(Ab + (size_t)(lr + 64) * K + (k0 + lk));
        float4 b0 = *(const float4*)(Bb + (size_t)lr        * K + (k0 + lk));
        float4 b1 = *(const float4*)(Bb + (size_t)(lr + 64) * K + (k0 + lk));
        __syncthreads();
        As[(lk + 0) * 132 + lr] = a0.x;
        As[(lk + 1) * 132 + lr] = a0.y;
        As[(lk + 2) * 132 + lr] = a0.z;
        As[(lk + 3) * 132 + lr] = a0.w;
        As[(lk + 0) * 132 + lr + 64] = a1.x;
        As[(lk + 1) * 132 + lr + 64] = a1.y;
        As[(lk + 2) * 132 + lr + 64] = a1.z;
        As[(lk + 3) * 132 + lr + 64] = a1.w;
        Bs[(lk + 0) * 132 + lr] = b0.x;
        Bs[(lk + 1) * 132 + lr] = b0.y;
        Bs[(lk + 2) * 132 + lr] = b0.z;
        Bs[(lk + 3) * 132 + lr] = b0.w;
        Bs[(lk + 0) * 132 + lr + 64] = b1.x;
        Bs[(lk + 1) * 132 + lr + 64] = b1.y;
        Bs[(lk + 2) * 132 + lr + 64] = b1.z;
        Bs[(lk + 3) * 132 + lr + 64] = b1.w;
        __syncthreads();

#pragma unroll
        for (int k = 0; k < 16; k++) {
            float4 av0 = *(const float4*)&As[k * 132 + ty * 8];
            float4 av1 = *(const float4*)&As[k * 132 + ty * 8 + 4];
            float4 bv0 = *(const float4*)&Bs[k * 132 + tx * 8];
            float4 bv1 = *(const float4*)&Bs[k * 132 + tx * 8 + 4];
            float a[8] = {av0.x, av0.y, av0.z, av0.w, av1.x, av1.y, av1.z, av1.w};
            float b[8] = {bv0.x, bv0.y, bv0.z, bv0.w, bv1.x, bv1.y, bv1.z, bv1.w};
#pragma unroll
            for (int i = 0; i < 8; i++)
#pragma unroll
                for (int j = 0; j < 8; j++)
                    acc[i][j] = fmaf(a[i], b[j], acc[i][j]);
        }
    }

    const int crow = blockIdx.y * 128 + ty * 8;
    const int ccol = blockIdx.x * 128 + tx * 8;
#pragma unroll
    for (int i = 0; i < 8; i++) {
        float4 c0 = make_float4(acc[i][0], acc[i][1], acc[i][2], acc[i][3]);
        float4 c1 = make_float4(acc[i][4], acc[i][5], acc[i][6], acc[i][7]);
        *(float4*)(C + (size_t)(crow + i) * N + ccol)     = c0;
        *(float4*)(C + (size_t)(crow + i) * N + ccol + 4) = c1;
    }
}

// ---------------------------------------------------------------------------
// Flash attention, fp32 exact. Grid (S/64, H). 256 threads.
// BM=64 queries resident, BN=64 keys per iteration, Hd=128.
// Thread (ty,tx): score rows ty*4+i, score cols tx+16*j; O cols tx*8+c.
// smem: Qs[64][132], Ks[64][132] (reused for V), Ps[64][65].
// ---------------------------------------------------------------------------
__global__ __launch_bounds__(256, 1)
void attn_kernel()
{
    extern __shared__ __align__(16) float sm[];
    float* Qs = sm;                  // 64*132
    float* Ks = sm + 64 * 132;       // 64*132  (K tile, then V tile)
    float* Ps = sm + 2 * 64 * 132;   // 64*65

    const int t  = threadIdx.x;
    const int tx = t & 15;
    const int ty = t >> 4;
    const int qb = blockIdx.x * 64;
    const int h  = blockIdx.y;
    const size_t hoff = (size_t)h * HD;

    // Load Q tile (coalesced, conflict-free float4 stores)
    for (int i = t; i < 64 * 32; i += 256) {
        int r = i >> 5;
        int c = (i & 31) << 2;
        *(float4*)&Qs[r * 132 + c] =
            *(const float4*)(g_Q + (size_t)(qb + r) * D_MODEL + hoff + c);
    }

    float m[4], l[4], o[4][8];
#pragma unroll
    for (int i = 0; i < 4; i++) {
        m[i] = -1e30f;
        l[i] = 0.f;
#pragma unroll
        for (int c = 0; c < 8; c++) o[i][c] = 0.f;
    }

    const float scale = 0.08838834764831845f;  // 1/sqrt(128)

    for (int kb = 0; kb < S_LEN; kb += 64) {
        __syncthreads();  // previous PV done with Ks/Ps
        for (int i = t; i < 64 * 32; i += 256) {
            int r = i >> 5;
            int c = (i & 31) << 2;
            *(float4*)&Ks[r * 132 + c] =
                *(const float4*)(g_K + (size_t)(kb + r) * D_MODEL + hoff + c);
        }
        __syncthreads();

        // S = Q K^T  (4x4 per thread)
        float s[4][4];
#pragma unroll
        for (int i = 0; i < 4; i++)
#pragma unroll
            for (int j = 0; j < 4; j++) s[i][j] = 0.f;

#pragma unroll 2
        for (int d = 0; d < HD; d += 4) {
            float4 q[4], kk[4];
#pragma unroll
            for (int i = 0; i < 4; i++)
                q[i] = *(const float4*)&Qs[(ty * 4 + i) * 132 + d];
#pragma unroll
            for (int j = 0; j < 4; j++)
                kk[j] = *(const float4*)&Ks[(tx + 16 * j) * 132 + d];
#pragma unroll
            for (int i = 0; i < 4; i++)
#pragma unroll
                for (int j = 0; j < 4; j++) {
                    s[i][j] = fmaf(q[i].x, kk[j].x, s[i][j]);
                    s[i][j] = fmaf(q[i].y, kk[j].y, s[i][j]);
                    s[i][j] = fmaf(q[i].z, kk[j].z, s[i][j]);
                    s[i][j] = fmaf(q[i].w, kk[j].w, s[i][j]);
                }
        }

        // Online softmax per row; row stats reduced across the 16 tx lanes.
#pragma unroll
        for (int i = 0; i < 4; i++) {
            float rmax = -1e30f;
#pragma unroll
            for (int j = 0; j < 4; j++) {
                s[i][j] *= scale;
                rmax = fmaxf(rmax, s[i][j]);
            }
#pragma unroll
            for (int off = 8; off > 0; off >>= 1)
                rmax = fmaxf(rmax, __shfl_xor_sync(0xffffffffu, rmax, off));
            float mn    = fmaxf(m[i], rmax);
            float alpha = __expf(m[i] - mn);
            m[i] = mn;
            float rsum = 0.f;
#pragma unroll
            for (int j = 0; j < 4; j++) {
                s[i][j] = __expf(s[i][j] - mn);
                rsum += s[i][j];
                Ps[(ty * 4 + i) * 65 + tx + 16 * j] = s[i][j];
            }
#pragma unroll
            for (int off = 8; off > 0; off >>= 1)
                rsum += __shfl_xor_sync(0xffffffffu, rsum, off);
            l[i] = l[i] * alpha + rsum;
#pragma unroll
            for (int c = 0; c < 8; c++) o[i][c] *= alpha;
        }
        __syncthreads();  // scores done reading Ks; Ps complete

        // Load V tile over Ks
        for (int i = t; i < 64 * 32; i += 256) {
            int r = i >> 5;
            int c = (i & 31) << 2;
            *(float4*)&Ks[r * 132 + c] =
                *(const float4*)(g_V + (size_t)(kb + r) * D_MODEL + hoff + c);
        }
        __syncthreads();

        // O += P @ V
#pragma unroll 2
        for (int k = 0; k < 64; k++) {
            float p[4];
#pragma unroll
            for (int i = 0; i < 4; i++)
                p[i] = Ps[(ty * 4 + i) * 65 + k];
            float4 v0 = *(const float4*)&Ks[k * 132 + tx * 8];
            float4 v1 = *(const float4*)&Ks[k * 132 + tx * 8 + 4];
            float v[8] = {v0.x, v0.y, v0.z, v0.w, v1.x, v1.y, v1.z, v1.w};
#pragma unroll
            for (int i = 0; i < 4; i++)
#pragma unroll
                for (int c = 0; c < 8; c++)
                    o[i][c] = fmaf(p[i], v[c], o[i][c]);
        }
    }

    // Normalize and write O
#pragma unroll
    for (int i = 0; i < 4; i++) {
        float inv = 1.f / l[i];
        float4 r0 = make_float4(o[i][0] * inv, o[i][1] * inv, o[i][2] * inv, o[i][3] * inv);
        float4 r1 = make_float4(o[i][4] * inv, o[i][5] * inv, o[i][6] * inv, o[i][7] * inv);
        float* dst = g_O + (size_t)(qb + ty * 4 + i) * D_MODEL + hoff + tx * 8;
        *(float4*)dst       = r0;
        *(float4*)(dst + 4) = r1;
    }
}

// ---------------------------------------------------------------------------
extern "C" void kernel_launch(void* const* d_in, const int* in_sizes, int n_in,
                              void* d_out, int out_size)
{
    (void)in_sizes; (void)n_in; (void)out_size;
    const float* x  = (const float*)d_in[0];
    const float* wq = (const float*)d_in[1];
    const float* wk = (const float*)d_in[2];
    const float* wv = (const float*)d_in[3];
    const float* wo = (const float*)d_in[4];
    float* out = (float*)d_out;

    float *Qp = nullptr, *Kp = nullptr, *Vp = nullptr, *Op = nullptr;
    cudaGetSymbolAddress((void**)&Qp, g_Q);
    cudaGetSymbolAddress((void**)&Kp, g_K);
    cudaGetSymbolAddress((void**)&Vp, g_V);
    cudaGetSymbolAddress((void**)&Op, g_O);

    const size_t ATT_SMEM = (size_t)(2 * 64 * 132 + 64 * 65) * sizeof(float);  // 84224 B
    cudaFuncSetAttribute(attn_kernel,
                         cudaFuncAttributeMaxDynamicSharedMemorySize,
                         (int)ATT_SMEM);

    dim3 gg(D_MODEL / 128, S_LEN / 128);  // 16 x 16
    gemm_nt_128<<<gg, 256>>>(x,  wq, Qp, S_LEN, D_MODEL, D_MODEL);
    gemm_nt_128<<<gg, 256>>>(x,  wk, Kp, S_LEN, D_MODEL, D_MODEL);
    gemm_nt_128<<<gg, 256>>>(x,  wv, Vp, S_LEN, D_MODEL, D_MODEL);
    attn_kernel<<<dim3(S_LEN / 64, N_HEADS), 256, ATT_SMEM>>>();
    gemm_nt_128<<<gg, 256>>>(Op, wo, out, S_LEN, D_MODEL, D_MODEL);
}

// round 2
// speedup vs baseline: 2.6688x; 2.6688x over previous
#include <cuda_runtime.h>

#define D_MODEL 2048
#define S_LEN   2048
#define N_HEADS 16
#define HD      128

// Scratch (allocation-free rule: __device__ globals)
__device__ __align__(16) float g_Q[S_LEN * D_MODEL];
__device__ __align__(16) float g_K[S_LEN * D_MODEL];
__device__ __align__(16) float g_V[S_LEN * D_MODEL];
__device__ __align__(16) float g_O[S_LEN * D_MODEL];

// round-to-nearest fp32 -> tf32 (kept in a float container)
__device__ __forceinline__ float f2tf(float x) {
    unsigned r;
    asm("cvt.rna.tf32.f32 %0, %1;" : "=r"(r) : "f"(x));
    return __uint_as_float(r);
}

__device__ __forceinline__ void mma_tf32(float* c, const unsigned* a, const unsigned* b) {
    asm volatile(
        "mma.sync.aligned.m16n8k8.row.col.f32.tf32.tf32.f32 "
        "{%0,%1,%2,%3}, {%4,%5,%6,%7}, {%8,%9}, {%0,%1,%2,%3};\n"
        : "+f"(c[0]), "+f"(c[1]), "+f"(c[2]), "+f"(c[3])
        : "r"(a[0]), "r"(a[1]), "r"(a[2]), "r"(a[3]), "r"(b[0]), "r"(b[1]));
}

// ---------------------------------------------------------------------------
// C[M,N] = A[M,K] @ B[N,K]^T via tf32 mma.sync. 128x128 CTA tile, BK=32.
// 8 warps: warp grid 4(m) x 2(n), warp tile 32x64.
// smem As[m][k], Bs[n][k] with row stride 40 floats (40%32==8 -> conflict-free
// fragment reads: bank = 8*gid + tig).
// ---------------------------------------------------------------------------
__global__ __launch_bounds__(256, 2)
void gemm_tf32(const float* __restrict__ A, const float* __restrict__ B,
               float* __restrict__ C, int M, int N, int K)
{
    __shared__ __align__(16) float As[128 * 40];
    __shared__ __align__(16) float Bs[128 * 40];

    const int t    = threadIdx.x;
    const int lane = t & 31;
    const int wid  = t >> 5;
    const int wm   = (wid & 3) * 32;   // warp m offset
    const int wn   = (wid >> 2) * 64;  // warp n offset
    const int gid  = lane >> 2;
    const int tig  = lane & 3;

    const float* Ab = A + (size_t)(blockIdx.y * 128) * K;
    const float* Bb = B + (size_t)(blockIdx.x * 128) * K;

    float acc[2][8][4];
#pragma unroll
    for (int mt = 0; mt < 2; mt++)
#pragma unroll
        for (int nt = 0; nt < 8; nt++)
#pragma unroll
            for (int r = 0; r < 4; r++) acc[mt][nt][r] = 0.f;

    for (int k0 = 0; k0 < K; k0 += 32) {
        __syncthreads();
#pragma unroll
        for (int p = 0; p < 4; p++) {
            int idx = p * 256 + t;          // float4 id, 8 per row
            int row = idx >> 3;
            int c4  = (idx & 7) << 2;
            float4 va = *(const float4*)(Ab + (size_t)row * K + k0 + c4);
            float4 vb = *(const float4*)(Bb + (size_t)row * K + k0 + c4);
            *(float4*)&As[row * 40 + c4] =
                make_float4(f2tf(va.x), f2tf(va.y), f2tf(va.z), f2tf(va.w));
            *(float4*)&Bs[row * 40 + c4] =
                make_float4(f2tf(vb.x), f2tf(vb.y), f2tf(vb.z), f2tf(vb.w));
        }
        __syncthreads();

#pragma unroll
        for (int ks = 0; ks < 4; ks++) {
            const int kk = ks * 8;
            unsigned a[2][4];
#pragma unroll
            for (int mt = 0; mt < 2; mt++) {
                int m = wm + mt * 16;
                a[mt][0] = __float_as_uint(As[(m + gid)     * 40 + kk + tig]);
                a[mt][1] = __float_as_uint(As[(m + gid + 8) * 40 + kk + tig]);
                a[mt][2] = __float_as_uint(As[(m + gid)     * 40 + kk + tig + 4]);
                a[mt][3] = __float_as_uint(As[(m + gid + 8) * 40 + kk + tig + 4]);
            }
#pragma unroll
            for (int nt = 0; nt < 8; nt++) {
                int n = wn + nt * 8;
                unsigned b[2];
                b[0] = __float_as_uint(Bs[(n + gid) * 40 + kk + tig]);
                b[1] = __float_as_uint(Bs[(n + gid) * 40 + kk + tig + 4]);
                mma_tf32(acc[0][nt], a[0], b);
                mma_tf32(acc[1][nt], a[1], b);
            }
        }
    }

    const int brow = blockIdx.y * 128 + wm;
    const int bcol = blockIdx.x * 128 + wn;
#pragma unroll
    for (int mt = 0; mt < 2; mt++) {
#pragma unroll
        for (int nt = 0; nt < 8; nt++) {
            int row = brow + mt * 16 + gid;
            int col = bcol + nt * 8 + tig * 2;
            *(float2*)(C + (size_t)row * N + col) =
                make_float2(acc[mt][nt][0], acc[mt][nt][1]);
            *(float2*)(C + (size_t)(row + 8) * N + col) =
                make_float2(acc[mt][nt][2], acc[mt][nt][3]);
        }
    }
}

// ---------------------------------------------------------------------------
// Flash attention with tf32 mma. Grid (S/64, H), 128 threads (4 warps).
// Each warp owns 16 query rows -> softmax reductions stay inside the quad group.
// smem: Qs[64][136], KVs[64][136] (K tile then V tile), Ps[64][72].
// ---------------------------------------------------------------------------
#define QS_STRIDE 136
#define PS_STRIDE 72

__global__ __launch_bounds__(128, 1)
void attn_tf32()
{
    extern __shared__ __align__(16) float sm[];
    float* Qs  = sm;                       // 64*136
    float* KVs = sm + 64 * QS_STRIDE;      // 64*136
    float* Ps  = sm + 2 * 64 * QS_STRIDE;  // 64*72

    const int t    = threadIdx.x;
    const int lane = t & 31;
    const int wid  = t >> 5;
    const int gid  = lane >> 2;
    const int tig  = lane & 3;
    const int m0   = wid * 16 + gid;  // first owned row (local)
    const int m1   = m0 + 8;

    const int qb = blockIdx.x * 64;
    const size_t hoff = (size_t)blockIdx.y * HD;

    // Load Q tile (tf32-rounded)
#pragma unroll
    for (int p = 0; p < 16; p++) {
        int idx = p * 128 + t;
        int row = idx >> 5;
        int c4  = (idx & 31) << 2;
        float4 v = *(const float4*)(g_Q + (size_t)(qb + row) * D_MODEL + hoff + c4);
        *(float4*)&Qs[row * QS_STRIDE + c4] =
            make_float4(f2tf(v.x), f2tf(v.y), f2tf(v.z), f2tf(v.w));
    }

    float o[16][4];
#pragma unroll
    for (int nt = 0; nt < 16; nt++)
#pragma unroll
        for (int r = 0; r < 4; r++) o[nt][r] = 0.f;
    float mrow0 = -1e30f, mrow1 = -1e30f, lrow0 = 0.f, lrow1 = 0.f;

    const float scale = 0.08838834764831845f;  // 1/sqrt(128)

    for (int kb = 0; kb < S_LEN; kb += 64) {
        __syncthreads();  // prev PV done with KVs; Q ready (first iter)
#pragma unroll
        for (int p = 0; p < 16; p++) {
            int idx = p * 128 + t;
            int row = idx >> 5;
            int c4  = (idx & 31) << 2;
            float4 v = *(const float4*)(g_K + (size_t)(kb + row) * D_MODEL + hoff + c4);
            *(float4*)&KVs[row * QS_STRIDE + c4] =
                make_float4(f2tf(v.x), f2tf(v.y), f2tf(v.z), f2tf(v.w));
        }
        __syncthreads();

        // S = Q K^T : per warp 16x64, 8 n-tiles
        float sc[8][4];
#pragma unroll
        for (int nt = 0; nt < 8; nt++)
#pragma unroll
            for (int r = 0; r < 4; r++) sc[nt][r] = 0.f;

#pragma unroll
        for (int ks = 0; ks < 16; ks++) {
            const int kk = ks * 8;
            unsigned a[4];
            a[0] = __float_as_uint(Qs[m0 * QS_STRIDE + kk + tig]);
            a[1] = __float_as_uint(Qs[m1 * QS_STRIDE + kk + tig]);
            a[2] = __float_as_uint(Qs[m0 * QS_STRIDE + kk + tig + 4]);
            a[3] = __float_as_uint(Qs[m1 * QS_STRIDE + kk + tig + 4]);
#pragma unroll
            for (int nt = 0; nt < 8; nt++) {
                unsigned b[2];
                b[0] = __float_as_uint(KVs[(nt * 8 + gid) * QS_STRIDE + kk + tig]);
                b[1] = __float_as_uint(KVs[(nt * 8 + gid) * QS_STRIDE + kk + tig + 4]);
                mma_tf32(sc[nt], a, b);
            }
        }

        // Online softmax. Row r0 values: sc[nt][0..1]; row r1: sc[nt][2..3].
        float mx0 = -1e30f, mx1 = -1e30f;
#pragma unroll
        for (int nt = 0; nt < 8; nt++) {
            sc[nt][0] *= scale; sc[nt][1] *= scale;
            sc[nt][2] *= scale; sc[nt][3] *= scale;
            mx0 = fmaxf(mx0, fmaxf(sc[nt][0], sc[nt][1]));
            mx1 = fmaxf(mx1, fmaxf(sc[nt][2], sc[nt][3]));
        }
        mx0 = fmaxf(mx0, __shfl_xor_sync(0xffffffffu, mx0, 1));
        mx0 = fmaxf(mx0, __shfl_xor_sync(0xffffffffu, mx0, 2));
        mx1 = fmaxf(mx1, __shfl_xor_sync(0xffffffffu, mx1, 1));
        mx1 = fmaxf(mx1, __shfl_xor_sync(0xffffffffu, mx1, 2));

        float mn0 = fmaxf(mrow0, mx0), mn1 = fmaxf(mrow1, mx1);
        float al0 = __expf(mrow0 - mn0), al1 = __expf(mrow1 - mn1);
        mrow0 = mn0; mrow1 = mn1;

        float sum0 = 0.f, sum1 = 0.f;
#pragma unroll
        for (int nt = 0; nt < 8; nt++) {
            float p0 = __expf(sc[nt][0] - mn0);
            float p1 = __expf(sc[nt][1] - mn0);
            float p2 = __expf(sc[nt][2] - mn1);
            float p3 = __expf(sc[nt][3] - mn1);
            sum0 += p0 + p1; sum1 += p2 + p3;
            int col = nt * 8 + tig * 2;
            Ps[m0 * PS_STRIDE + col]     = f2tf(p0);
            Ps[m0 * PS_STRIDE + col + 1] = f2tf(p1);
            Ps[m1 * PS_STRIDE + col]     = f2tf(p2);
            Ps[m1 * PS_STRIDE + col + 1] = f2tf(p3);
        }
        sum0 += __shfl_xor_sync(0xffffffffu, sum0, 1);
        sum0 += __shfl_xor_sync(0xffffffffu, sum0, 2);
        sum1 += __shfl_xor_sync(0xffffffffu, sum1, 1);
        sum1 += __shfl_xor_sync(0xffffffffu, sum1, 2);
        lrow0 = lrow0 * al0 + sum0;
        lrow1 = lrow1 * al1 + sum1;
#pragma unroll
        for (int nt = 0; nt < 16; nt++) {
            o[nt][0] *= al0; o[nt][1] *= al0;
            o[nt][2] *= al1; o[nt][3] *= al1;
        }
        __syncthreads();  // all warps done reading KVs (K); Ps written

        // Load V tile over KVs
#pragma unroll
        for (int p = 0; p < 16; p++) {
            int idx = p * 128 + t;
            int row = idx >> 5;
            int c4  = (idx & 31) << 2;
            float4 v = *(const float4*)(g_V + (size_t)(kb + row) * D_MODEL + hoff + c4);
            *(float4*)&KVs[row * QS_STRIDE + c4] =
                make_float4(f2tf(v.x), f2tf(v.y), f2tf(v.z), f2tf(v.w));
        }
        __syncthreads();

        // O += P @ V : per warp 16x128, 16 n-tiles, 8 k-steps
#pragma unroll
        for (int ks = 0; ks < 8; ks++) {
            const int kk = ks * 8;
            unsigned a[4];
            a[0] = __float_as_uint(Ps[m0 * PS_STRIDE + kk + tig]);
            a[1] = __float_as_uint(Ps[m1 * PS_STRIDE + kk + tig]);
            a[2] = __float_as_uint(Ps[m0 * PS_STRIDE + kk + tig + 4]);
            a[3] = __float_as_uint(Ps[m1 * PS_STRIDE + kk + tig + 4]);
#pragma unroll
            for (int nt = 0; nt < 16; nt++) {
                unsigned b[2];
                b[0] = __float_as_uint(KVs[(kk + tig)     * QS_STRIDE + nt * 8 + gid]);
                b[1] = __float_as_uint(KVs[(kk + tig + 4) * QS_STRIDE + nt * 8 + gid]);
                mma_tf32(o[nt], a, b);
            }
        }
    }

    // Normalize and write O
    float inv0 = 1.f / lrow0, inv1 = 1.f / lrow1;
#pragma unroll
    for (int nt = 0; nt < 16; nt++) {
        int col = nt * 8 + tig * 2;
        float* d0 = g_O + (size_t)(qb + m0) * D_MODEL + hoff + col;
        float* d1 = g_O + (size_t)(qb + m1) * D_MODEL + hoff + col;
        *(float2*)d0 = make_float2(o[nt][0] * inv0, o[nt][1] * inv0);
        *(float2*)d1 = make_float2(o[nt][2] * inv1, o[nt][3] * inv1);
    }
}

// ---------------------------------------------------------------------------
extern "C" void kernel_launch(void* const* d_in, const int* in_sizes, int n_in,
                              void* d_out, int out_size)
{
    (void)in_sizes; (void)n_in; (void)out_size;
    const float* x  = (const float*)d_in[0];
    const float* wq = (const float*)d_in[1];
    const float* wk = (const float*)d_in[2];
    const float* wv = (const float*)d_in[3];
    const float* wo = (const float*)d_in[4];
    float* out = (float*)d_out;

    float *Qp = nullptr, *Kp = nullptr, *Vp = nullptr, *Op = nullptr;
    cudaGetSymbolAddress((void**)&Qp, g_Q);
    cudaGetSymbolAddress((void**)&Kp, g_K);
    cudaGetSymbolAddress((void**)&Vp, g_V);
    cudaGetSymbolAddress((void**)&Op, g_O);

    const size_t ATT_SMEM =
        (size_t)(2 * 64 * QS_STRIDE + 64 * PS_STRIDE) * sizeof(float);  // 88064 B
    cudaFuncSetAttribute(attn_tf32,
                         cudaFuncAttributeMaxDynamicSharedMemorySize,
                         (int)ATT_SMEM);

    dim3 gg(D_MODEL / 128, S_LEN / 128);  // 16 x 16
    gemm_tf32<<<gg, 256>>>(x,  wq, Qp, S_LEN, D_MODEL, D_MODEL);
    gemm_tf32<<<gg, 256>>>(x,  wk, Kp, S_LEN, D_MODEL, D_MODEL);
    gemm_tf32<<<gg, 256>>>(x,  wv, Vp, S_LEN, D_MODEL, D_MODEL);
    attn_tf32<<<dim3(S_LEN / 64, N_HEADS), 128, ATT_SMEM>>>();
    gemm_tf32<<<gg, 256>>>(Op, wo, out, S_LEN, D_MODEL, D_MODEL);
}

// round 4
// speedup vs baseline: 3.2927x; 1.2338x over previous
#include <cuda_runtime.h>

#define D_MODEL 2048
#define S_LEN   2048
#define N_HEADS 16
#define HD      128

__device__ __align__(16) float g_Q[S_LEN * D_MODEL];
__device__ __align__(16) float g_K[S_LEN * D_MODEL];
__device__ __align__(16) float g_V[S_LEN * D_MODEL];
__device__ __align__(16) float g_O[S_LEN * D_MODEL];

__device__ __forceinline__ float f2tf(float x) {
    unsigned r;
    asm("cvt.rna.tf32.f32 %0, %1;" : "=r"(r) : "f"(x));
    return __uint_as_float(r);
}

__device__ __forceinline__ void mma_tf32(float* c, const unsigned* a, const unsigned* b) {
    asm volatile(
        "mma.sync.aligned.m16n8k8.row.col.f32.tf32.tf32.f32 "
        "{%0,%1,%2,%3}, {%4,%5,%6,%7}, {%8,%9}, {%0,%1,%2,%3};\n"
        : "+f"(c[0]), "+f"(c[1]), "+f"(c[2]), "+f"(c[3])
        : "r"(a[0]), "r"(a[1]), "r"(a[2]), "r"(a[3]), "r"(b[0]), "r"(b[1]));
}

// ldmatrix.x4 on b16: each 8x8 b16 tile == 8x4 tf32 tile with per-thread
// distribution (row t/4, col t%4) == the tf32 mma fragment layout.
__device__ __forceinline__ void ldsm4(unsigned* r, const float* p) {
    unsigned addr = (unsigned)__cvta_generic_to_shared(p);
    asm volatile("ldmatrix.sync.aligned.m8n8.x4.shared.b16 {%0,%1,%2,%3}, [%4];"
                 : "=r"(r[0]), "=r"(r[1]), "=r"(r[2]), "=r"(r[3]) : "r"(addr));
}

// ---------------------------------------------------------------------------
// C[M,N] = A[M,K] @ B[N,K]^T, tf32 mma + ldmatrix. 128x128 CTA, BK=32.
// 8 warps, warp grid 4(m) x 2(n), warp tile 32x64. smem stride 36 (36%32==4:
// ldmatrix 8-row phases hit distinct bank groups; float4 stores conflict-free).
// Register prefetch of next gmem tile overlaps LDG with MMA.
// ---------------------------------------------------------------------------
__global__ __launch_bounds__(256, 2)
void gemm_tf32(const float* __restrict__ A, const float* __restrict__ B,
               float* __restrict__ C, int M, int N, int K)
{
    __shared__ __align__(16) float As[128 * 36];
    __shared__ __align__(16) float Bs[128 * 36];

    const int t    = threadIdx.x;
    const int lane = t & 31;
    const int wid  = t >> 5;
    const int wm   = (wid & 3) * 32;
    const int wn   = (wid >> 2) * 64;

    // ldmatrix lane address patterns
    const int la7  = lane & 7;
    const int lb   = (lane >> 3) & 1;
    const int lc   = lane >> 4;
    const int arow = la7 + 8 * lb;   // A: rows (m..m+15), col +4*lc
    const int acol = 4 * lc;
    const int brow = la7 + 8 * lc;   // B: rows (n..n+15), col +4*lb
    const int bcol = 4 * lb;

    const float* Ab = A + (size_t)(blockIdx.y * 128) * K;
    const float* Bb = B + (size_t)(blockIdx.x * 128) * K;

    const int ldrow = t >> 3;            // 0..31 (+p*32)
    const int ldc4  = (t & 7) << 2;      // 0..28

    float acc[2][8][4];
#pragma unroll
    for (int mt = 0; mt < 2; mt++)
#pragma unroll
        for (int nt = 0; nt < 8; nt++)
#pragma unroll
            for (int r = 0; r < 4; r++) acc[mt][nt][r] = 0.f;

    float4 pa[4], pb[4];
#pragma unroll
    for (int p = 0; p < 4; p++) {
        int row = p * 32 + ldrow;
        pa[p] = *(const float4*)(Ab + (size_t)row * K + ldc4);
        pb[p] = *(const float4*)(Bb + (size_t)row * K + ldc4);
    }

    for (int k0 = 0; k0 < K; k0 += 32) {
        __syncthreads();
#pragma unroll
        for (int p = 0; p < 4; p++) {
            int row = p * 32 + ldrow;
            *(float4*)&As[row * 36 + ldc4] =
                make_float4(f2tf(pa[p].x), f2tf(pa[p].y), f2tf(pa[p].z), f2tf(pa[p].w));
            *(float4*)&Bs[row * 36 + ldc4] =
                make_float4(f2tf(pb[p].x), f2tf(pb[p].y), f2tf(pb[p].z), f2tf(pb[p].w));
        }
        __syncthreads();

        if (k0 + 32 < K) {
#pragma unroll
            for (int p = 0; p < 4; p++) {
                int row = p * 32 + ldrow;
                pa[p] = *(const float4*)(Ab + (size_t)row * K + k0 + 32 + ldc4);
                pb[p] = *(const float4*)(Bb + (size_t)row * K + k0 + 32 + ldc4);
            }
        }

#pragma unroll
        for (int ks = 0; ks < 4; ks++) {
            const int kk = ks * 8;
            unsigned a0[4], a1[4];
            ldsm4(a0, &As[(wm + arow)      * 36 + kk + acol]);
            ldsm4(a1, &As[(wm + 16 + arow) * 36 + kk + acol]);
#pragma unroll
            for (int ntp = 0; ntp < 4; ntp++) {
                unsigned b[4];
                ldsm4(b, &Bs[(wn + ntp * 16 + brow) * 36 + kk + bcol]);
                mma_tf32(acc[0][2 * ntp],     a0, b);
                mma_tf32(acc[0][2 * ntp + 1], a0, b + 2);
                mma_tf32(acc[1][2 * ntp],     a1, b);
                mma_tf32(acc[1][2 * ntp + 1], a1, b + 2);
            }
        }
    }

    const int gid = lane >> 2, tig = lane & 3;
    const int crow = blockIdx.y * 128 + wm;
    const int ccol = blockIdx.x * 128 + wn;
#pragma unroll
    for (int mt = 0; mt < 2; mt++) {
#pragma unroll
        for (int nt = 0; nt < 8; nt++) {
            int row = crow + mt * 16 + gid;
            int col = ccol + nt * 8 + tig * 2;
            *(float2*)(C + (size_t)row * N + col) =
                make_float2(acc[mt][nt][0], acc[mt][nt][1]);
            *(float2*)(C + (size_t)(row + 8) * N + col) =
                make_float2(acc[mt][nt][2], acc[mt][nt][3]);
        }
    }
}

// ---------------------------------------------------------------------------
// Flash attention, tf32 mma + ldmatrix. Grid (S/64, H), 128 threads.
// Q/K tiles stride 132 (ldmatrix-friendly), V tile stride 136 (scalar-LDS
// friendly: bank = 8*tig + gid, conflict-free), P stride 68.
// ---------------------------------------------------------------------------
#define Q_STR  132
#define V_STR  136
#define P_STR  68

__global__ __launch_bounds__(128, 2)
void attn_tf32()
{
    extern __shared__ __align__(16) float sm[];
    float* Qs  = sm;                   // 64*132
    float* KVs = sm + 64 * Q_STR;      // 64*136 (K tile @132 stride, V @136)
    float* Ps  = sm + 64 * (Q_STR + V_STR);  // 64*68

    const int t    = threadIdx.x;
    const int lane = t & 31;
    const int wid  = t >> 5;
    const int gid  = lane >> 2;
    const int tig  = lane & 3;
    const int m0   = wid * 16 + gid;
    const int m1   = m0 + 8;

    const int la7  = lane & 7;
    const int lb   = (lane >> 3) & 1;
    const int lc   = lane >> 4;
    const int arow = la7 + 8 * lb;
    const int acol = 4 * lc;
    const int brow = la7 + 8 * lc;
    const int bcol = 4 * lb;

    const int qb = blockIdx.x * 64;
    const size_t hoff = (size_t)blockIdx.y * HD;

    const int ldrow = t >> 5;        // warp-uniform row within 4-row group
    const int ldc4  = (t & 31) << 2;

#pragma unroll
    for (int p = 0; p < 16; p++) {
        int row = p * 4 + ldrow;
        float4 v = *(const float4*)(g_Q + (size_t)(qb + row) * D_MODEL + hoff + ldc4);
        *(float4*)&Qs[row * Q_STR + ldc4] =
            make_float4(f2tf(v.x), f2tf(v.y), f2tf(v.z), f2tf(v.w));
    }

    float o[16][4];
#pragma unroll
    for (int nt = 0; nt < 16; nt++)
#pragma unroll
        for (int r = 0; r < 4; r++) o[nt][r] = 0.f;
    float mrow0 = -1e30f, mrow1 = -1e30f, lrow0 = 0.f, lrow1 = 0.f;

    const float scale = 0.08838834764831845f;  // 1/sqrt(128)

    for (int kb = 0; kb < S_LEN; kb += 64) {
        __syncthreads();
#pragma unroll
        for (int p = 0; p < 16; p++) {
            int row = p * 4 + ldrow;
            float4 v = *(const float4*)(g_K + (size_t)(kb + row) * D_MODEL + hoff + ldc4);
            *(float4*)&KVs[row * Q_STR + ldc4] =
                make_float4(f2tf(v.x), f2tf(v.y), f2tf(v.z), f2tf(v.w));
        }
        __syncthreads();

        // S = Q K^T : 16x64 per warp
        float sc[8][4];
#pragma unroll
        for (int nt = 0; nt < 8; nt++)
#pragma unroll
            for (int r = 0; r < 4; r++) sc[nt][r] = 0.f;

#pragma unroll
        for (int ks = 0; ks < 16; ks++) {
            const int kk = ks * 8;
            unsigned a[4];
            ldsm4(a, &Qs[(wid * 16 + arow) * Q_STR + kk + acol]);
#pragma unroll
            for (int ntp = 0; ntp < 4; ntp++) {
                unsigned b[4];
                ldsm4(b, &KVs[(ntp * 16 + brow) * Q_STR + kk + bcol]);
                mma_tf32(sc[2 * ntp],     a, b);
                mma_tf32(sc[2 * ntp + 1], a, b + 2);
            }
        }

        // Online softmax (rows m0: sc[][0..1], m1: sc[][2..3])
        float mx0 = -1e30f, mx1 = -1e30f;
#pragma unroll
        for (int nt = 0; nt < 8; nt++) {
            sc[nt][0] *= scale; sc[nt][1] *= scale;
            sc[nt][2] *= scale; sc[nt][3] *= scale;
            mx0 = fmaxf(mx0, fmaxf(sc[nt][0], sc[nt][1]));
            mx1 = fmaxf(mx1, fmaxf(sc[nt][2], sc[nt][3]));
        }
        mx0 = fmaxf(mx0, __shfl_xor_sync(0xffffffffu, mx0, 1));
        mx0 = fmaxf(mx0, __shfl_xor_sync(0xffffffffu, mx0, 2));
        mx1 = fmaxf(mx1, __shfl_xor_sync(0xffffffffu, mx1, 1));
        mx1 = fmaxf(mx1, __shfl_xor_sync(0xffffffffu, mx1, 2));

        float mn0 = fmaxf(mrow0, mx0), mn1 = fmaxf(mrow1, mx1);
        float al0 = __expf(mrow0 - mn0), al1 = __expf(mrow1 - mn1);
        mrow0 = mn0; mrow1 = mn1;

        float sum0 = 0.f, sum1 = 0.f;
#pragma unroll
        for (int nt = 0; nt < 8; nt++) {
            float p0 = __expf(sc[nt][0] - mn0);
            float p1 = __expf(sc[nt][1] - mn0);
            float p2 = __expf(sc[nt][2] - mn1);
            float p3 = __expf(sc[nt][3] - mn1);
            sum0 += p0 + p1; sum1 += p2 + p3;
            int col = nt * 8 + tig * 2;
            *(float2*)&Ps[m0 * P_STR + col] = make_float2(f2tf(p0), f2tf(p1));
            *(float2*)&Ps[m1 * P_STR + col] = make_float2(f2tf(p2), f2tf(p3));
        }
        sum0 += __shfl_xor_sync(0xffffffffu, sum0, 1);
        sum0 += __shfl_xor_sync(0xffffffffu, sum0, 2);
        sum1 += __shfl_xor_sync(0xffffffffu, sum1, 1);
        sum1 += __shfl_xor_sync(0xffffffffu, sum1, 2);
        lrow0 = lrow0 * al0 + sum0;
        lrow1 = lrow1 * al1 + sum1;
#pragma unroll
        for (int nt = 0; nt < 16; nt++) {
            o[nt][0] *= al0; o[nt][1] *= al0;
            o[nt][2] *= al1; o[nt][3] *= al1;
        }
        __syncthreads();  // K reads + P writes complete

        // V tile (stride 136)
#pragma unroll
        for (int p = 0; p < 16; p++) {
            int row = p * 4 + ldrow;
            float4 v = *(const float4*)(g_V + (size_t)(kb + row) * D_MODEL + hoff + ldc4);
            *(float4*)&KVs[row * V_STR + ldc4] =
                make_float4(f2tf(v.x), f2tf(v.y), f2tf(v.z), f2tf(v.w));
        }
        __syncthreads();

        // O += P @ V : 16x128 per warp
#pragma unroll
        for (int ks = 0; ks < 8; ks++) {
            const int kk = ks * 8;
            unsigned a[4];
            ldsm4(a, &Ps[(wid * 16 + arow) * P_STR + kk + acol]);
            const float* vr0 = &KVs[(kk + tig)     * V_STR + gid];
            const float* vr1 = &KVs[(kk + tig + 4) * V_STR + gid];
#pragma unroll
            for (int nt = 0; nt < 16; nt++) {
                unsigned b[2];
                b[0] = __float_as_uint(vr0[nt * 8]);
                b[1] = __float_as_uint(vr1[nt * 8]);
                mma_tf32(o[nt], a, b);
            }
        }
    }

    float inv0 = 1.f / lrow0, inv1 = 1.f / lrow1;
#pragma unroll
    for (int nt = 0; nt < 16; nt++) {
        int col = nt * 8 + tig * 2;
        float* d0 = g_O + (size_t)(qb + m0) * D_MODEL + hoff + col;
        float* d1 = g_O + (size_t)(qb + m1) * D_MODEL + hoff + col;
        *(float2*)d0 = make_float2(o[nt][0] * inv0, o[nt][1] * inv0);
        *(float2*)d1 = make_float2(o[nt][2] * inv1, o[nt][3] * inv1);
    }
}

// ---------------------------------------------------------------------------
extern "C" void kernel_launch(void* const* d_in, const int* in_sizes, int n_in,
                              void* d_out, int out_size)
{
    (void)in_sizes; (void)n_in; (void)out_size;
    const float* x  = (const float*)d_in[0];
    const float* wq = (const float*)d_in[1];
    const float* wk = (const float*)d_in[2];
    const float* wv = (const float*)d_in[3];
    const float* wo = (const float*)d_in[4];
    float* out = (float*)d_out;

    float *Qp = nullptr, *Kp = nullptr, *Vp = nullptr, *Op = nullptr;
    cudaGetSymbolAddress((void**)&Qp, g_Q);
    cudaGetSymbolAddress((void**)&Kp, g_K);
    cudaGetSymbolAddress((void**)&Vp, g_V);
    cudaGetSymbolAddress((void**)&Op, g_O);

    const size_t ATT_SMEM = (size_t)(64 * (Q_STR + V_STR + P_STR)) * sizeof(float);  // 86016
    cudaFuncSetAttribute(attn_tf32,
                         cudaFuncAttributeMaxDynamicSharedMemorySize,
                         (int)ATT_SMEM);

    dim3 gg(D_MODEL / 128, S_LEN / 128);
    gemm_tf32<<<gg, 256>>>(x,  wq, Qp, S_LEN, D_MODEL, D_MODEL);
    gemm_tf32<<<gg, 256>>>(x,  wk, Kp, S_LEN, D_MODEL, D_MODEL);
    gemm_tf32<<<gg, 256>>>(x,  wv, Vp, S_LEN, D_MODEL, D_MODEL);
    attn_tf32<<<dim3(S_LEN / 64, N_HEADS), 128, ATT_SMEM>>>();
    gemm_tf32<<<gg, 256>>>(Op, wo, out, S_LEN, D_MODEL, D_MODEL);
}

// round 6
// speedup vs baseline: 3.7676x; 1.1442x over previous
#include <cuda_runtime.h>

#define D_MODEL 2048
#define S_LEN   2048
#define N_HEADS 16
#define HD      128

// Scratch (allocation-free rule: __device__ globals)
__device__ __align__(16) float g_Q[S_LEN * D_MODEL];
__device__ __align__(16) float g_K[S_LEN * D_MODEL];
__device__ __align__(16) float g_V[S_LEN * D_MODEL];
__device__ __align__(16) float g_O[S_LEN * D_MODEL];
__device__ __align__(16) float g_Xr[S_LEN * D_MODEL];
__device__ __align__(16) float g_Wq[D_MODEL * D_MODEL];
__device__ __align__(16) float g_Wk[D_MODEL * D_MODEL];
__device__ __align__(16) float g_Wv[D_MODEL * D_MODEL];
__device__ __align__(16) float g_Wo[D_MODEL * D_MODEL];

__device__ __forceinline__ float f2tf(float x) {
    unsigned r;
    asm("cvt.rna.tf32.f32 %0, %1;" : "=r"(r) : "f"(x));
    return __uint_as_float(r);
}

__device__ __forceinline__ void mma_tf32(float* c, const unsigned* a, const unsigned* b) {
    asm volatile(
        "mma.sync.aligned.m16n8k8.row.col.f32.tf32.tf32.f32 "
        "{%0,%1,%2,%3}, {%4,%5,%6,%7}, {%8,%9}, {%0,%1,%2,%3};\n"
        : "+f"(c[0]), "+f"(c[1]), "+f"(c[2]), "+f"(c[3])
        : "r"(a[0]), "r"(a[1]), "r"(a[2]), "r"(a[3]), "r"(b[0]), "r"(b[1]));
}

__device__ __forceinline__ void ldsm4(unsigned* r, const float* p) {
    unsigned addr = (unsigned)__cvta_generic_to_shared(p);
    asm volatile("ldmatrix.sync.aligned.m8n8.x4.shared.b16 {%0,%1,%2,%3}, [%4];"
                 : "=r"(r[0]), "=r"(r[1]), "=r"(r[2]), "=r"(r[3]) : "r"(addr));
}

__device__ __forceinline__ void cpa16(unsigned dst, const void* src) {
    asm volatile("cp.async.cg.shared.global [%0], [%1], 16;" :: "r"(dst), "l"(src));
}
__device__ __forceinline__ void cpa_commit() {
    asm volatile("cp.async.commit_group;");
}
template <int N>
__device__ __forceinline__ void cpa_wait() {
    asm volatile("cp.async.wait_group %0;" :: "n"(N));
}

// ---------------------------------------------------------------------------
// One-shot tf32 rounding pass (pays the cvt cost once; unlocks raw cp.async)
// ---------------------------------------------------------------------------
__global__ __launch_bounds__(256)
void round_tf32_k(const float4* __restrict__ s, float4* __restrict__ d, int n4)
{
    int i = blockIdx.x * blockDim.x + threadIdx.x;
    if (i < n4) {
        float4 v = s[i];
        d[i] = make_float4(f2tf(v.x), f2tf(v.y), f2tf(v.z), f2tf(v.w));
    }
}

// ---------------------------------------------------------------------------
// C[M,N] = A[M,K] @ B[N,K]^T, tf32 mma + ldmatrix + 3-stage cp.async pipeline.
// Inputs MUST be pre-rounded to tf32. 128x128 CTA, BK=32, 8 warps.
// smem: 3 stages x (As 128x36 + Bs 128x36) = 110592 B, 2 CTAs/SM.
// ---------------------------------------------------------------------------
#define G_TILE 4608  // 128*36 floats

__global__ __launch_bounds__(256, 2)
void gemm_tf32(const float* __restrict__ A, const float* __restrict__ B,
               float* __restrict__ C, int M, int N, int K, int round_out)
{
    extern __shared__ __align__(16) float smem[];  // 3*2*G_TILE floats

    const int t    = threadIdx.x;
    const int lane = t & 31;
    const int wid  = t >> 5;
    const int wm   = (wid & 3) * 32;
    const int wn   = (wid >> 2) * 64;

    const int la7  = lane & 7;
    const int lb   = (lane >> 3) & 1;
    const int lc   = lane >> 4;
    const int arow = la7 + 8 * lb;
    const int acol = 4 * lc;
    const int brow = la7 + 8 * lc;
    const int bcol = 4 * lb;

    const float* Ab = A + (size_t)(blockIdx.y * 128) * K;
    const float* Bb = B + (size_t)(blockIdx.x * 128) * K;

    const unsigned smem_u = (unsigned)__cvta_generic_to_shared(smem);
    const int ldrow = t >> 3;        // 0..31
    const int ldc4  = (t & 7) << 2;  // 0..28

    float acc[2][8][4];
#pragma unroll
    for (int mt = 0; mt < 2; mt++)
#pragma unroll
        for (int nt = 0; nt < 8; nt++)
#pragma unroll
            for (int r = 0; r < 4; r++) acc[mt][nt][r] = 0.f;

    auto issue = [&](int kt, int st) {
        unsigned as_u = smem_u + (unsigned)(st * 2 * G_TILE) * 4u;
        unsigned bs_u = as_u + (unsigned)G_TILE * 4u;
        const float* Ak = Ab + kt * 32;
        const float* Bk = Bb + kt * 32;
#pragma unroll
        for (int p = 0; p < 4; p++) {
            int row = p * 32 + ldrow;
            cpa16(as_u + (unsigned)(row * 36 + ldc4) * 4u, Ak + (size_t)row * K + ldc4);
            cpa16(bs_u + (unsigned)(row * 36 + ldc4) * 4u, Bk + (size_t)row * K + ldc4);
        }
    };

    const int nk = K >> 5;  // 64
    issue(0, 0); cpa_commit();
    issue(1, 1); cpa_commit();
    issue(2, 2); cpa_commit();

    int st = 0;
    for (int kt = 0; kt < nk; kt++) {
        cpa_wait<2>();
        __syncthreads();
        const float* As_ = smem + st * 2 * G_TILE;
        const float* Bs_ = As_ + G_TILE;
#pragma unroll
        for (int ks = 0; ks < 4; ks++) {
            const int kk = ks * 8;
            unsigned a0[4], a1[4];
            ldsm4(a0, &As_[(wm + arow)      * 36 + kk + acol]);
            ldsm4(a1, &As_[(wm + 16 + arow) * 36 + kk + acol]);
#pragma unroll
            for (int ntp = 0; ntp < 4; ntp++) {
                unsigned b[4];
                ldsm4(b, &Bs_[(wn + ntp * 16 + brow) * 36 + kk + bcol]);
                mma_tf32(acc[0][2 * ntp],     a0, b);
                mma_tf32(acc[0][2 * ntp + 1], a0, b + 2);
                mma_tf32(acc[1][2 * ntp],     a1, b);
                mma_tf32(acc[1][2 * ntp + 1], a1, b + 2);
            }
        }
        __syncthreads();
        if (kt + 3 < nk) issue(kt + 3, st);
        cpa_commit();
        st++; if (st == 3) st = 0;
    }

    const int gid = lane >> 2, tig = lane & 3;
    const int crow = blockIdx.y * 128 + wm;
    const int ccol = blockIdx.x * 128 + wn;
#pragma unroll
    for (int mt = 0; mt < 2; mt++) {
#pragma unroll
        for (int nt = 0; nt < 8; nt++) {
            int row = crow + mt * 16 + gid;
            int col = ccol + nt * 8 + tig * 2;
            float v0 = acc[mt][nt][0], v1 = acc[mt][nt][1];
            float v2 = acc[mt][nt][2], v3 = acc[mt][nt][3];
            if (round_out) {
                v0 = f2tf(v0); v1 = f2tf(v1); v2 = f2tf(v2); v3 = f2tf(v3);
            }
            *(float2*)(C + (size_t)row * N + col)       = make_float2(v0, v1);
            *(float2*)(C + (size_t)(row + 8) * N + col) = make_float2(v2, v3);
        }
    }
}

// ---------------------------------------------------------------------------
// Flash attention, tf32 mma + ldmatrix + cp.async software pipeline.
// Grid (S/64, H), 128 threads. Q/K/V already tf32-rounded in gmem.
// smem: Qs[64][132] + Ks[64][132] + Vs[64][136] = 102400 B, 2 CTAs/SM.
// P never touches smem: S-tile C-frags -> PV A-frags via quad shuffles.
// Pipeline: K[i+1] loads during PV[i]; V[i+1] loads during QK[i+1].
// ---------------------------------------------------------------------------
#define Q_STR 132
#define K_STR 132
#define V_STR 136

__global__ __launch_bounds__(128, 2)
void attn_tf32()
{
    extern __shared__ __align__(16) float sm[];
    float* Qs = sm;                      // 64*132
    float* Ks = sm + 64 * Q_STR;         // 64*132
    float* Vs = sm + 64 * (Q_STR + K_STR);  // 64*136

    const int t    = threadIdx.x;
    const int lane = t & 31;
    const int wid  = t >> 5;
    const int gid  = lane >> 2;
    const int tig  = lane & 3;
    const int m0   = wid * 16 + gid;
    const int m1   = m0 + 8;

    const int la7  = lane & 7;
    const int lb   = (lane >> 3) & 1;
    const int lc   = lane >> 4;
    const int arow = la7 + 8 * lb;
    const int acol = 4 * lc;
    const int brow = la7 + 8 * lc;
    const int bcol = 4 * lb;

    const int qb = blockIdx.x * 64;
    const size_t hoff = (size_t)blockIdx.y * HD;

    const unsigned smem_u = (unsigned)__cvta_generic_to_shared(sm);
    const unsigned k_u = smem_u + (unsigned)(64 * Q_STR) * 4u;
    const unsigned v_u = smem_u + (unsigned)(64 * (Q_STR + K_STR)) * 4u;

    const int ldrow = t >> 5;         // 0..3
    const int ldc4  = (t & 31) << 2;  // 0..124

    auto issueK = [&](int kb2) {
#pragma unroll
        for (int p = 0; p < 16; p++) {
            int row = p * 4 + ldrow;
            cpa16(k_u + (unsigned)(row * K_STR + ldc4) * 4u,
                  g_K + (size_t)(kb2 + row) * D_MODEL + hoff + ldc4);
        }
    };
    auto issueV = [&](int kb2) {
#pragma unroll
        for (int p = 0; p < 16; p++) {
            int row = p * 4 + ldrow;
            cpa16(v_u + (unsigned)(row * V_STR + ldc4) * 4u,
                  g_V + (size_t)(kb2 + row) * D_MODEL + hoff + ldc4);
        }
    };

    // Prologue: Q, K0, V0
    {
#pragma unroll
        for (int p = 0; p < 16; p++) {
            int row = p * 4 + ldrow;
            cpa16(smem_u + (unsigned)(row * Q_STR + ldc4) * 4u,
                  g_Q + (size_t)(qb + row) * D_MODEL + hoff + ldc4);
        }
        cpa_commit();
        issueK(0); cpa_commit();
        issueV(0); cpa_commit();
    }
    cpa_wait<1>();   // Q + K0 arrived (V0 may be in flight)
    __syncthreads();

    float o[16][4];
#pragma unroll
    for (int nt = 0; nt < 16; nt++)
#pragma unroll
        for (int r = 0; r < 4; r++) o[nt][r] = 0.f;
    float mrow0 = -1e30f, mrow1 = -1e30f, lrow0 = 0.f, lrow1 = 0.f;

    const float scale = 0.08838834764831845f;  // 1/sqrt(128)

    for (int kb = 0; kb < S_LEN; kb += 64) {
        // ---- S = Q K^T : 16x64 per warp ----
        float sc[8][4];
#pragma unroll
        for (int nt = 0; nt < 8; nt++)
#pragma unroll
            for (int r = 0; r < 4; r++) sc[nt][r] = 0.f;

#pragma unroll
        for (int ks = 0; ks < 16; ks++) {
            const int kk = ks * 8;
            unsigned a[4];
            ldsm4(a, &Qs[(wid * 16 + arow) * Q_STR + kk + acol]);
#pragma unroll
            for (int ntp = 0; ntp < 4; ntp++) {
                unsigned b[4];
                ldsm4(b, &Ks[(ntp * 16 + brow) * K_STR + kk + bcol]);
                mma_tf32(sc[2 * ntp],     a, b);
                mma_tf32(sc[2 * ntp + 1], a, b + 2);
            }
        }

        // ---- Online softmax (rows m0: sc[][0..1], m1: sc[][2..3]) ----
        float mx0 = -1e30f, mx1 = -1e30f;
#pragma unroll
        for (int nt = 0; nt < 8; nt++) {
            sc[nt][0] *= scale; sc[nt][1] *= scale;
            sc[nt][2] *= scale; sc[nt][3] *= scale;
            mx0 = fmaxf(mx0, fmaxf(sc[nt][0], sc[nt][1]));
            mx1 = fmaxf(mx1, fmaxf(sc[nt][2], sc[nt][3]));
        }
        mx0 = fmaxf(mx0, __shfl_xor_sync(0xffffffffu, mx0, 1));
        mx0 = fmaxf(mx0, __shfl_xor_sync(0xffffffffu, mx0, 2));
        mx1 = fmaxf(mx1, __shfl_xor_sync(0xffffffffu, mx1, 1));
        mx1 = fmaxf(mx1, __shfl_xor_sync(0xffffffffu, mx1, 2));

        float mn0 = fmaxf(mrow0, mx0), mn1 = fmaxf(mrow1, mx1);
        float al0 = __expf(mrow0 - mn0), al1 = __expf(mrow1 - mn1);
        mrow0 = mn0; mrow1 = mn1;

        float sum0 = 0.f, sum1 = 0.f;
#pragma unroll
        for (int nt = 0; nt < 8; nt++) {
            sc[nt][0] = __expf(sc[nt][0] - mn0);
            sc[nt][1] = __expf(sc[nt][1] - mn0);
            sc[nt][2] = __expf(sc[nt][2] - mn1);
            sc[nt][3] = __expf(sc[nt][3] - mn1);
            sum0 += sc[nt][0] + sc[nt][1];
            sum1 += sc[nt][2] + sc[nt][3];
        }
        sum0 += __shfl_xor_sync(0xffffffffu, sum0, 1);
        sum0 += __shfl_xor_sync(0xffffffffu, sum0, 2);
        sum1 += __shfl_xor_sync(0xffffffffu, sum1, 1);
        sum1 += __shfl_xor_sync(0xffffffffu, sum1, 2);
        lrow0 = lrow0 * al0 + sum0;
        lrow1 = lrow1 * al1 + sum1;
#pragma unroll
        for (int nt = 0; nt < 16; nt++) {
            o[nt][0] *= al0; o[nt][1] *= al0;
            o[nt][2] *= al1; o[nt][3] *= al1;
        }

        // ---- Permute S c-frags -> PV a-frags (quad shuffles, no smem) ----
        unsigned pa[8][4];
        {
            const int l1 = (gid << 2) + (tig >> 1);
            const int l2 = l1 + 2;
            const bool e = tig & 1;
#pragma unroll
            for (int ks = 0; ks < 8; ks++) {
                float v0a = __shfl_sync(0xffffffffu, sc[ks][0], l1);
                float v0b = __shfl_sync(0xffffffffu, sc[ks][1], l1);
                float v1a = __shfl_sync(0xffffffffu, sc[ks][2], l1);
                float v1b = __shfl_sync(0xffffffffu, sc[ks][3], l1);
                float v2a = __shfl_sync(0xffffffffu, sc[ks][0], l2);
                float v2b = __shfl_sync(0xffffffffu, sc[ks][1], l2);
                float v3a = __shfl_sync(0xffffffffu, sc[ks][2], l2);
                float v3b = __shfl_sync(0xffffffffu, sc[ks][3], l2);
                pa[ks][0] = __float_as_uint(f2tf(e ? v0b : v0a));
                pa[ks][1] = __float_as_uint(f2tf(e ? v1b : v1a));
                pa[ks][2] = __float_as_uint(f2tf(e ? v2b : v2a));
                pa[ks][3] = __float_as_uint(f2tf(e ? v3b : v3a));
            }
        }

        __syncthreads();                       // all warps done reading Ks
        if (kb + 64 < S_LEN) issueK(kb + 64);  // K[i+1] overlaps PV
        cpa_commit();
        cpa_wait<1>();                         // V[i] arrived
        __syncthreads();

        // ---- O += P @ V : 16x128 per warp ----
#pragma unroll
        for (int ks = 0; ks < 8; ks++) {
            const int kk = ks * 8;
            const float* vr0 = &Vs[(kk + tig)     * V_STR + gid];
            const float* vr1 = &Vs[(kk + tig + 4) * V_STR + gid];
#pragma unroll
            for (int nt = 0; nt < 16; nt++) {
                unsigned b[2];
                b[0] = __float_as_uint(vr0[nt * 8]);
                b[1] = __float_as_uint(vr1[nt * 8]);
                mma_tf32(o[nt], pa[ks], b);
            }
        }

        __syncthreads();                       // all warps done reading Vs
        if (kb + 64 < S_LEN) issueV(kb + 64);  // V[i+1] overlaps next QK
        cpa_commit();
        cpa_wait<1>();                         // K[i+1] arrived
        __syncthreads();
    }

    // Normalize, round to tf32 (final GEMM reads raw), write O
    float inv0 = 1.f / lrow0, inv1 = 1.f / lrow1;
#pragma unroll
    for (int nt = 0; nt < 16; nt++) {
        int col = nt * 8 + tig * 2;
        float* d0 = g_O + (size_t)(qb + m0) * D_MODEL + hoff + col;
        float* d1 = g_O + (size_t)(qb + m1) * D_MODEL + hoff + col;
        *(float2*)d0 = make_float2(f2tf(o[nt][0] * inv0), f2tf(o[nt][1] * inv0));
        *(float2*)d1 = make_float2(f2tf(o[nt][2] * inv1), f2tf(o[nt][3] * inv1));
    }
}

// ---------------------------------------------------------------------------
extern "C" void kernel_launch(void* const* d_in, const int* in_sizes, int n_in,
                              void* d_out, int out_size)
{
    (void)in_sizes; (void)n_in; (void)out_size;
    const float* x  = (const float*)d_in[0];
    const float* wq = (const float*)d_in[1];
    const float* wk = (const float*)d_in[2];
    const float* wv = (const float*)d_in[3];
    const float* wo = (const float*)d_in[4];
    float* out = (float*)d_out;

    float *Qp, *Kp, *Vp, *Op, *Xr, *Wq, *Wk, *Wv, *Wo;
    cudaGetSymbolAddress((void**)&Qp, g_Q);
    cudaGetSymbolAddress((void**)&Kp, g_K);
    cudaGetSymbolAddress((void**)&Vp, g_V);
    cudaGetSymbolAddress((void**)&Op, g_O);
    cudaGetSymbolAddress((void**)&Xr, g_Xr);
    cudaGetSymbolAddress((void**)&Wq, g_Wq);
    cudaGetSymbolAddress((void**)&Wk, g_Wk);
    cudaGetSymbolAddress((void**)&Wv, g_Wv);
    cudaGetSymbolAddress((void**)&Wo, g_Wo);

    const size_t GEMM_SMEM = (size_t)(3 * 2 * G_TILE) * sizeof(float);  // 110592
    const size_t ATT_SMEM  = (size_t)(64 * (Q_STR + K_STR + V_STR)) * sizeof(float);  // 102400
    cudaFuncSetAttribute(gemm_tf32, cudaFuncAttributeMaxDynamicSharedMemorySize, (int)GEMM_SMEM);
    cudaFuncSetAttribute(attn_tf32, cudaFuncAttributeMaxDynamicSharedMemorySize, (int)ATT_SMEM);

    // One-shot tf32 rounding of all GEMM inputs
    const int n4 = S_LEN * D_MODEL / 4;  // all five tensors are 2048x2048
    round_tf32_k<<<n4 / 256, 256>>>((const float4*)x,  (float4*)Xr, n4);
    round_tf32_k<<<n4 / 256, 256>>>((const float4*)wq, (float4*)Wq, n4);
    round_tf32_k<<<n4 / 256, 256>>>((const float4*)wk, (float4*)Wk, n4);
    round_tf32_k<<<n4 / 256, 256>>>((const float4*)wv, (float4*)Wv, n4);
    round_tf32_k<<<n4 / 256, 256>>>((const float4*)wo, (float4*)Wo, n4);

    dim3 gg(D_MODEL / 128, S_LEN / 128);  // 16 x 16
    gemm_tf32<<<gg, 256, GEMM_SMEM>>>(Xr, Wq, Qp, S_LEN, D_MODEL, D_MODEL, 1);
    gemm_tf32<<<gg, 256, GEMM_SMEM>>>(Xr, Wk, Kp, S_LEN, D_MODEL, D_MODEL, 1);
    gemm_tf32<<<gg, 256, GEMM_SMEM>>>(Xr, Wv, Vp, S_LEN, D_MODEL, D_MODEL, 1);
    attn_tf32<<<dim3(S_LEN / 64, N_HEADS), 128, ATT_SMEM>>>();
    gemm_tf32<<<gg, 256, GEMM_SMEM>>>(Op, Wo, out, S_LEN, D_MODEL, D_MODEL, 0);
}

// round 8
// speedup vs baseline: 3.8279x; 1.0160x over previous
#include <cuda_runtime.h>

#define D_MODEL 2048
#define S_LEN   2048
#define N_HEADS 16
#define HD      128

// Scratch (allocation-free rule: __device__ globals)
__device__ __align__(16) float g_Q[S_LEN * D_MODEL];
__device__ __align__(16) float g_K[S_LEN * D_MODEL];
__device__ __align__(16) float g_V[S_LEN * D_MODEL];
__device__ __align__(16) float g_O[S_LEN * D_MODEL];
__device__ __align__(16) float g_Xr[S_LEN * D_MODEL];
__device__ __align__(16) float g_Wq[D_MODEL * D_MODEL];
__device__ __align__(16) float g_Wk[D_MODEL * D_MODEL];
__device__ __align__(16) float g_Wv[D_MODEL * D_MODEL];
__device__ __align__(16) float g_Wo[D_MODEL * D_MODEL];

__device__ __forceinline__ float f2tf(float x) {
    unsigned r;
    asm("cvt.rna.tf32.f32 %0, %1;" : "=r"(r) : "f"(x));
    return __uint_as_float(r);
}

__device__ __forceinline__ void mma_tf32(float* c, const unsigned* a, const unsigned* b) {
    asm volatile(
        "mma.sync.aligned.m16n8k8.row.col.f32.tf32.tf32.f32 "
        "{%0,%1,%2,%3}, {%4,%5,%6,%7}, {%8,%9}, {%0,%1,%2,%3};\n"
        : "+f"(c[0]), "+f"(c[1]), "+f"(c[2]), "+f"(c[3])
        : "r"(a[0]), "r"(a[1]), "r"(a[2]), "r"(a[3]), "r"(b[0]), "r"(b[1]));
}

__device__ __forceinline__ void ldsm4(unsigned* r, const float* p) {
    unsigned addr = (unsigned)__cvta_generic_to_shared(p);
    asm volatile("ldmatrix.sync.aligned.m8n8.x4.shared.b16 {%0,%1,%2,%3}, [%4];"
                 : "=r"(r[0]), "=r"(r[1]), "=r"(r[2]), "=r"(r[3]) : "r"(addr));
}

__device__ __forceinline__ void cpa16(unsigned dst, const void* src) {
    asm volatile("cp.async.cg.shared.global [%0], [%1], 16;" :: "r"(dst), "l"(src));
}
__device__ __forceinline__ void cpa_commit() {
    asm volatile("cp.async.commit_group;");
}
template <int N>
__device__ __forceinline__ void cpa_wait() {
    asm volatile("cp.async.wait_group %0;" :: "n"(N));
}

// ---------------------------------------------------------------------------
// Fused one-shot tf32 rounding of all 5 input tensors (blockIdx.y selects)
// ---------------------------------------------------------------------------
__global__ __launch_bounds__(256)
void round5_k(const float4* __restrict__ x,  float4* __restrict__ xr,
              const float4* __restrict__ wq, float4* __restrict__ wqr,
              const float4* __restrict__ wk, float4* __restrict__ wkr,
              const float4* __restrict__ wv, float4* __restrict__ wvr,
              const float4* __restrict__ wo, float4* __restrict__ wor, int n4)
{
    int i = blockIdx.x * blockDim.x + threadIdx.x;
    if (i >= n4) return;
    const float4* s;
    float4* d;
    switch (blockIdx.y) {
        case 0: s = x;  d = xr;  break;
        case 1: s = wq; d = wqr; break;
        case 2: s = wk; d = wkr; break;
        case 3: s = wv; d = wvr; break;
        default: s = wo; d = wor; break;
    }
    float4 v = s[i];
    d[i] = make_float4(f2tf(v.x), f2tf(v.y), f2tf(v.z), f2tf(v.w));
}

// ---------------------------------------------------------------------------
// C[2048,2048] = A @ B^T, tf32 mma + ldmatrix + 3-stage cp.async pipeline with
// ONE syncthreads per k-iter (issue-before-compute, distance 2).
// blockIdx.z selects (B, C) pair -> fused QKV projection in one launch.
// 128x128 CTA, BK=32, 8 warps (4m x 2n), warp tile 32x64, smem stride 36.
// smem: 3 stages x 2 x 128x36 floats = 110592 B, 2 CTAs/SM.
// ---------------------------------------------------------------------------
#define G_TILE 4608  // 128*36 floats

__global__ __launch_bounds__(256, 2)
void gemm_tf32(const float* __restrict__ A,
               const float* __restrict__ B0, const float* __restrict__ B1,
               const float* __restrict__ B2,
               float* __restrict__ C0, float* __restrict__ C1,
               float* __restrict__ C2, int round_out)
{
    extern __shared__ __align__(16) float smem[];  // 3*2*G_TILE floats

    const float* B = (blockIdx.z == 0) ? B0 : (blockIdx.z == 1) ? B1 : B2;
    float*       C = (blockIdx.z == 0) ? C0 : (blockIdx.z == 1) ? C1 : C2;
    const int K = 2048, N = 2048;

    const int t    = threadIdx.x;
    const int lane = t & 31;
    const int wid  = t >> 5;
    const int wm   = (wid & 3) * 32;
    const int wn   = (wid >> 2) * 64;

    const int la7  = lane & 7;
    const int lb   = (lane >> 3) & 1;
    const int lc   = lane >> 4;
    const int arow = la7 + 8 * lb;
    const int acol = 4 * lc;
    const int brow = la7 + 8 * lc;
    const int bcol = 4 * lb;

    const float* Ab = A + (size_t)(blockIdx.y * 128) * K;
    const float* Bb = B + (size_t)(blockIdx.x * 128) * K;

    const unsigned smem_u = (unsigned)__cvta_generic_to_shared(smem);
    const int ldrow = t >> 3;        // 0..31
    const int ldc4  = (t & 7) << 2;  // 0..28

    float acc[2][8][4];
#pragma unroll
    for (int mt = 0; mt < 2; mt++)
#pragma unroll
        for (int nt = 0; nt < 8; nt++)
#pragma unroll
            for (int r = 0; r < 4; r++) acc[mt][nt][r] = 0.f;

    auto issue = [&](int kt, int st) {
        unsigned as_u = smem_u + (unsigned)(st * 2 * G_TILE) * 4u;
        unsigned bs_u = as_u + (unsigned)G_TILE * 4u;
        const float* Ak = Ab + kt * 32;
        const float* Bk = Bb + kt * 32;
#pragma unroll
        for (int p = 0; p < 4; p++) {
            int row = p * 32 + ldrow;
            cpa16(as_u + (unsigned)(row * 36 + ldc4) * 4u, Ak + (size_t)row * K + ldc4);
            cpa16(bs_u + (unsigned)(row * 36 + ldc4) * 4u, Bk + (size_t)row * K + ldc4);
        }
    };

    const int nk = K >> 5;  // 64
    issue(0, 0); cpa_commit();
    issue(1, 1); cpa_commit();

    int st = 0;
    for (int kt = 0; kt < nk; kt++) {
        cpa_wait<1>();        // group kt arrived (kt+1 may be in flight)
        __syncthreads();      // stage st visible to all; stage (kt-1)%3 free
        if (kt + 2 < nk) {
            int st2 = st + 2; if (st2 >= 3) st2 -= 3;
            issue(kt + 2, st2);
        }
        cpa_commit();

        const float* As_ = smem + st * 2 * G_TILE;
        const float* Bs_ = As_ + G_TILE;
#pragma unroll
        for (int ks = 0; ks < 4; ks++) {
            const int kk = ks * 8;
            unsigned a0[4], a1[4];
            ldsm4(a0, &As_[(wm + arow)      * 36 + kk + acol]);
            ldsm4(a1, &As_[(wm + 16 + arow) * 36 + kk + acol]);
#pragma unroll
            for (int ntp = 0; ntp < 4; ntp++) {
                unsigned b[4];
                ldsm4(b, &Bs_[(wn + ntp * 16 + brow) * 36 + kk + bcol]);
                mma_tf32(acc[0][2 * ntp],     a0, b);
                mma_tf32(acc[0][2 * ntp + 1], a0, b + 2);
                mma_tf32(acc[1][2 * ntp],     a1, b);
                mma_tf32(acc[1][2 * ntp + 1], a1, b + 2);
            }
        }
        st++; if (st == 3) st = 0;
    }

    const int gid = lane >> 2, tig = lane & 3;
    const int crow = blockIdx.y * 128 + wm;
    const int ccol = blockIdx.x * 128 + wn;
#pragma unroll
    for (int mt = 0; mt < 2; mt++) {
#pragma unroll
        for (int nt = 0; nt < 8; nt++) {
            int row = crow + mt * 16 + gid;
            int col = ccol + nt * 8 + tig * 2;
            float v0 = acc[mt][nt][0], v1 = acc[mt][nt][1];
            float v2 = acc[mt][nt][2], v3 = acc[mt][nt][3];
            if (round_out) {
                v0 = f2tf(v0); v1 = f2tf(v1); v2 = f2tf(v2); v3 = f2tf(v3);
            }
            *(float2*)(C + (size_t)row * N + col)       = make_float2(v0, v1);
            *(float2*)(C + (size_t)(row + 8) * N + col) = make_float2(v2, v3);
        }
    }
}

// ---------------------------------------------------------------------------
// Flash attention (unchanged from R6 passing kernel): tf32 mma.sync +
// ldmatrix + cp.async pipeline. Grid (S/64, H), 128 threads.
// ---------------------------------------------------------------------------
#define Q_STR 132
#define K_STR 132
#define V_STR 136

__global__ __launch_bounds__(128, 2)
void attn_tf32()
{
    extern __shared__ __align__(16) float sm[];
    float* Qs = sm;
    float* Ks = sm + 64 * Q_STR;
    float* Vs = sm + 64 * (Q_STR + K_STR);

    const int t    = threadIdx.x;
    const int lane = t & 31;
    const int wid  = t >> 5;
    const int gid  = lane >> 2;
    const int tig  = lane & 3;
    const int m0   = wid * 16 + gid;
    const int m1   = m0 + 8;

    const int la7  = lane & 7;
    const int lb   = (lane >> 3) & 1;
    const int lc   = lane >> 4;
    const int arow = la7 + 8 * lb;
    const int acol = 4 * lc;
    const int brow = la7 + 8 * lc;
    const int bcol = 4 * lb;

    const int qb = blockIdx.x * 64;
    const size_t hoff = (size_t)blockIdx.y * HD;

    const unsigned smem_u = (unsigned)__cvta_generic_to_shared(sm);
    const unsigned k_u = smem_u + (unsigned)(64 * Q_STR) * 4u;
    const unsigned v_u = smem_u + (unsigned)(64 * (Q_STR + K_STR)) * 4u;

    const int ldrow = t >> 5;
    const int ldc4  = (t & 31) << 2;

    auto issueK = [&](int kb2) {
#pragma unroll
        for (int p = 0; p < 16; p++) {
            int row = p * 4 + ldrow;
            cpa16(k_u + (unsigned)(row * K_STR + ldc4) * 4u,
                  g_K + (size_t)(kb2 + row) * D_MODEL + hoff + ldc4);
        }
    };
    auto issueV = [&](int kb2) {
#pragma unroll
        for (int p = 0; p < 16; p++) {
            int row = p * 4 + ldrow;
            cpa16(v_u + (unsigned)(row * V_STR + ldc4) * 4u,
                  g_V + (size_t)(kb2 + row) * D_MODEL + hoff + ldc4);
        }
    };

    {
#pragma unroll
        for (int p = 0; p < 16; p++) {
            int row = p * 4 + ldrow;
            cpa16(smem_u + (unsigned)(row * Q_STR + ldc4) * 4u,
                  g_Q + (size_t)(qb + row) * D_MODEL + hoff + ldc4);
        }
        cpa_commit();
        issueK(0); cpa_commit();
        issueV(0); cpa_commit();
    }
    cpa_wait<1>();
    __syncthreads();

    float o[16][4];
#pragma unroll
    for (int nt = 0; nt < 16; nt++)
#pragma unroll
        for (int r = 0; r < 4; r++) o[nt][r] = 0.f;
    float mrow0 = -1e30f, mrow1 = -1e30f, lrow0 = 0.f, lrow1 = 0.f;

    const float scale = 0.08838834764831845f;

    for (int kb = 0; kb < S_LEN; kb += 64) {
        float sc[8][4];
#pragma unroll
        for (int nt = 0; nt < 8; nt++)
#pragma unroll
            for (int r = 0; r < 4; r++) sc[nt][r] = 0.f;

#pragma unroll
        for (int ks = 0; ks < 16; ks++) {
            const int kk = ks * 8;
            unsigned a[4];
            ldsm4(a, &Qs[(wid * 16 + arow) * Q_STR + kk + acol]);
#pragma unroll
            for (int ntp = 0; ntp < 4; ntp++) {
                unsigned b[4];
                ldsm4(b, &Ks[(ntp * 16 + brow) * K_STR + kk + bcol]);
                mma_tf32(sc[2 * ntp],     a, b);
                mma_tf32(sc[2 * ntp + 1], a, b + 2);
            }
        }

        float mx0 = -1e30f, mx1 = -1e30f;
#pragma unroll
        for (int nt = 0; nt < 8; nt++) {
            sc[nt][0] *= scale; sc[nt][1] *= scale;
            sc[nt][2] *= scale; sc[nt][3] *= scale;
            mx0 = fmaxf(mx0, fmaxf(sc[nt][0], sc[nt][1]));
            mx1 = fmaxf(mx1, fmaxf(sc[nt][2], sc[nt][3]));
        }
        mx0 = fmaxf(mx0, __shfl_xor_sync(0xffffffffu, mx0, 1));
        mx0 = fmaxf(mx0, __shfl_xor_sync(0xffffffffu, mx0, 2));
        mx1 = fmaxf(mx1, __shfl_xor_sync(0xffffffffu, mx1, 1));
        mx1 = fmaxf(mx1, __shfl_xor_sync(0xffffffffu, mx1, 2));

        float mn0 = fmaxf(mrow0, mx0), mn1 = fmaxf(mrow1, mx1);
        float al0 = __expf(mrow0 - mn0), al1 = __expf(mrow1 - mn1);
        mrow0 = mn0; mrow1 = mn1;

        float sum0 = 0.f, sum1 = 0.f;
#pragma unroll
        for (int nt = 0; nt < 8; nt++) {
            sc[nt][0] = __expf(sc[nt][0] - mn0);
            sc[nt][1] = __expf(sc[nt][1] - mn0);
            sc[nt][2] = __expf(sc[nt][2] - mn1);
            sc[nt][3] = __expf(sc[nt][3] - mn1);
            sum0 += sc[nt][0] + sc[nt][1];
            sum1 += sc[nt][2] + sc[nt][3];
        }
        sum0 += __shfl_xor_sync(0xffffffffu, sum0, 1);
        sum0 += __shfl_xor_sync(0xffffffffu, sum0, 2);
        sum1 += __shfl_xor_sync(0xffffffffu, sum1, 1);
        sum1 += __shfl_xor_sync(0xffffffffu, sum1, 2);
        lrow0 = lrow0 * al0 + sum0;
        lrow1 = lrow1 * al1 + sum1;
#pragma unroll
        for (int nt = 0; nt < 16; nt++) {
            o[nt][0] *= al0; o[nt][1] *= al0;
            o[nt][2] *= al1; o[nt][3] *= al1;
        }

        unsigned pa[8][4];
        {
            const int l1 = (gid << 2) + (tig >> 1);
            const int l2 = l1 + 2;
            const bool e = tig & 1;
#pragma unroll
            for (int ks = 0; ks < 8; ks++) {
                float v0a = __shfl_sync(0xffffffffu, sc[ks][0], l1);
                float v0b = __shfl_sync(0xffffffffu, sc[ks][1], l1);
                float v1a = __shfl_sync(0xffffffffu, sc[ks][2], l1);
                float v1b = __shfl_sync(0xffffffffu, sc[ks][3], l1);
                float v2a = __shfl_sync(0xffffffffu, sc[ks][0], l2);
                float v2b = __shfl_sync(0xffffffffu, sc[ks][1], l2);
                float v3a = __shfl_sync(0xffffffffu, sc[ks][2], l2);
                float v3b = __shfl_sync(0xffffffffu, sc[ks][3], l2);
                pa[ks][0] = __float_as_uint(f2tf(e ? v0b : v0a));
                pa[ks][1] = __float_as_uint(f2tf(e ? v1b : v1a));
                pa[ks][2] = __float_as_uint(f2tf(e ? v2b : v2a));
                pa[ks][3] = __float_as_uint(f2tf(e ? v3b : v3a));
            }
        }

        __syncthreads();
        if (kb + 64 < S_LEN) issueK(kb + 64);
        cpa_commit();
        cpa_wait<1>();
        __syncthreads();

#pragma unroll
        for (int ks = 0; ks < 8; ks++) {
            const int kk = ks * 8;
            const float* vr0 = &Vs[(kk + tig)     * V_STR + gid];
            const float* vr1 = &Vs[(kk + tig + 4) * V_STR + gid];
#pragma unroll
            for (int nt = 0; nt < 16; nt++) {
                unsigned b[2];
                b[0] = __float_as_uint(vr0[nt * 8]);
                b[1] = __float_as_uint(vr1[nt * 8]);
                mma_tf32(o[nt], pa[ks], b);
            }
        }

        __syncthreads();
        if (kb + 64 < S_LEN) issueV(kb + 64);
        cpa_commit();
        cpa_wait<1>();
        __syncthreads();
    }

    float inv0 = 1.f / lrow0, inv1 = 1.f / lrow1;
#pragma unroll
    for (int nt = 0; nt < 16; nt++) {
        int col = nt * 8 + tig * 2;
        float* d0 = g_O + (size_t)(qb + m0) * D_MODEL + hoff + col;
        float* d1 = g_O + (size_t)(qb + m1) * D_MODEL + hoff + col;
        *(float2*)d0 = make_float2(f2tf(o[nt][0] * inv0), f2tf(o[nt][1] * inv0));
        *(float2*)d1 = make_float2(f2tf(o[nt][2] * inv1), f2tf(o[nt][3] * inv1));
    }
}

// ---------------------------------------------------------------------------
extern "C" void kernel_launch(void* const* d_in, const int* in_sizes, int n_in,
                              void* d_out, int out_size)
{
    (void)in_sizes; (void)n_in; (void)out_size;
    const float* x  = (const float*)d_in[0];
    const float* wq = (const float*)d_in[1];
    const float* wk = (const float*)d_in[2];
    const float* wv = (const float*)d_in[3];
    const float* wo = (const float*)d_in[4];
    float* out = (float*)d_out;

    float *Qp, *Kp, *Vp, *Op, *Xr, *Wq, *Wk, *Wv, *Wo;
    cudaGetSymbolAddress((void**)&Qp, g_Q);
    cudaGetSymbolAddress((void**)&Kp, g_K);
    cudaGetSymbolAddress((void**)&Vp, g_V);
    cudaGetSymbolAddress((void**)&Op, g_O);
    cudaGetSymbolAddress((void**)&Xr, g_Xr);
    cudaGetSymbolAddress((void**)&Wq, g_Wq);
    cudaGetSymbolAddress((void**)&Wk, g_Wk);
    cudaGetSymbolAddress((void**)&Wv, g_Wv);
    cudaGetSymbolAddress((void**)&Wo, g_Wo);

    const size_t GEMM_SMEM = (size_t)(3 * 2 * G_TILE) * sizeof(float);  // 110592
    const size_t ATT_SMEM  = (size_t)(64 * (Q_STR + K_STR + V_STR)) * sizeof(float);  // 102400
    cudaFuncSetAttribute(gemm_tf32, cudaFuncAttributeMaxDynamicSharedMemorySize, (int)GEMM_SMEM);
    cudaFuncSetAttribute(attn_tf32, cudaFuncAttributeMaxDynamicSharedMemorySize, (int)ATT_SMEM);

    // Fused one-shot tf32 rounding of all 5 GEMM inputs
    const int n4 = S_LEN * D_MODEL / 4;
    round5_k<<<dim3(n4 / 256, 5), 256>>>(
        (const float4*)x,  (float4*)Xr,
        (const float4*)wq, (float4*)Wq,
        (const float4*)wk, (float4*)Wk,
        (const float4*)wv, (float4*)Wv,
        (const float4*)wo, (float4*)Wo, n4);

    // Fused QKV projection: one launch, blockIdx.z selects weight/output
    dim3 gqkv(D_MODEL / 128, S_LEN / 128, 3);  // 16 x 16 x 3
    gemm_tf32<<<gqkv, 256, GEMM_SMEM>>>(Xr, Wq, Wk, Wv, Qp, Kp, Vp, 1);

    attn_tf32<<<dim3(S_LEN / 64, N_HEADS), 128, ATT_SMEM>>>();

    dim3 go(D_MODEL / 128, S_LEN / 128, 1);
    gemm_tf32<<<go, 256, GEMM_SMEM>>>(Op, Wo, Wo, Wo, out, out, out, 0);
}